// round 6
// baseline (speedup 1.0000x reference)
#include <cuda_runtime.h>
#include <cuda_fp16.h>
#include <cstdint>

// Problem dims (fixed per reference)
#define DIM_M 512
#define DIM_K 4096
#define DIM_N 11008

#define CTA_M 128
#define CTA_N 128
#define KSTEP 64                 // halves per K step
#define ITERS (DIM_K / KSTEP)    // 64
#define STAGES 3                 // A cp.async ring depth
#define GRID_MT (DIM_M / CTA_M)  // 4
#define GRID_NT (DIM_N / CTA_N)  // 86

// SMEM rows padded to 144B -> 8-row ldmatrix bases distinct mod 128 (conflict-free)
#define ROWB 144
#define TILE_BYTES (128 * ROWB)                  // 18432
// A: 3 stages ; B: 2 buffers
#define OFF_B (STAGES * TILE_BYTES)              // 55296
#define SMEM_TOTAL (OFF_B + 2 * TILE_BYTES)      // 92160

// x converted to fp16, row-major [512][4096]
__device__ __align__(16) __half g_x16[DIM_M * DIM_K];

__device__ __forceinline__ uint32_t smem_u32(const void* p) {
    uint32_t a;
    asm("{ .reg .u64 t; cvta.to.shared.u64 t, %1; cvt.u32.u64 %0, t; }" : "=r"(a) : "l"(p));
    return a;
}

__device__ __forceinline__ void cp_async16(uint32_t dst, const void* src) {
    asm volatile("cp.async.cg.shared.global [%0], [%1], 16;" :: "r"(dst), "l"(src));
}
__device__ __forceinline__ void cp_commit() { asm volatile("cp.async.commit_group;"); }

__device__ __forceinline__ void ldsm4(uint32_t* r, uint32_t addr) {
    asm volatile("ldmatrix.sync.aligned.m8n8.x4.shared.b16 {%0,%1,%2,%3}, [%4];"
                 : "=r"(r[0]), "=r"(r[1]), "=r"(r[2]), "=r"(r[3]) : "r"(addr));
}

__device__ __forceinline__ void mma16816(float* d, const uint32_t* a, const uint32_t* b) {
    asm volatile(
        "mma.sync.aligned.m16n8k16.row.col.f32.f16.f16.f32 "
        "{%0,%1,%2,%3}, {%4,%5,%6,%7}, {%8,%9}, {%0,%1,%2,%3};"
        : "+f"(d[0]), "+f"(d[1]), "+f"(d[2]), "+f"(d[3])
        : "r"(a[0]), "r"(a[1]), "r"(a[2]), "r"(a[3]), "r"(b[0]), "r"(b[1]));
}

__device__ __forceinline__ uint32_t pack2(float a, float b) {
    __half2 h = __floats2half2_rn(a, b);
    return *reinterpret_cast<uint32_t*>(&h);
}

// ---------------- kernel 0: x fp32 -> fp16 row-major ----------------
__global__ void __launch_bounds__(256) convert_x_kernel(const float* __restrict__ x) {
    int gid = blockIdx.x * blockDim.x + threadIdx.x;
    const float4* src = reinterpret_cast<const float4*>(x) + gid * 2;
    float4 f0 = __ldg(src);
    float4 f1 = __ldg(src + 1);
    uint4 v;
    v.x = pack2(f0.x, f0.y);
    v.y = pack2(f0.z, f0.w);
    v.z = pack2(f1.x, f1.y);
    v.w = pack2(f1.z, f1.w);
    reinterpret_cast<uint4*>(g_x16)[gid] = v;
}

// ---------------- kernel 1: fused dequant + fp16 HMMA GEMM ----------------
__global__ void __launch_bounds__(512, 1) gemm_kernel(const int* __restrict__ w,
                                                      const float* __restrict__ saz,
                                                      float* __restrict__ out) {
    extern __shared__ __align__(1024) char smem[];
    const uint32_t sb = smem_u32(smem);
    const int tid = threadIdx.x;
    const int wid = tid >> 5;
    const int lid = tid & 31;

    // m-fast grid ordering: 4 CTAs sharing a weight N-tile run concurrently -> L2 reuse
    const int mtile = blockIdx.x & 3;
    const int ntile = blockIdx.x >> 2;
    const int mbase = mtile * CTA_M;
    const int nbase = ntile * CTA_N;

    // 4x4 warp grid, warp tile 32x32
    const int m0w = (wid & 3) * 32;
    const int n0w = (wid >> 2) * 32;

    // ---- A loader (cp.async): tile 128 rows x 8 chunks(16B); 2 chunks/thread ----
    const int r0 = tid >> 3;         // 0..63
    const int c  = tid & 7;          // 0..7
    const __half* aG = g_x16 + (size_t)(mbase + r0) * DIM_K + c * 8;
    const uint32_t a_stg_off = (uint32_t)r0 * ROWB + c * 16;
    const size_t a_gstep = (size_t)64 * DIM_K;
    const uint32_t a_sstep = 64u * ROWB;

    // ---- B loader (LDG int32 + dequant + STS): row = tid>>2, quarter = tid&3 ----
    const int brow = tid >> 2;       // 0..127
    const int bq = tid & 3;          // 16 ints each
    const int4* wG = reinterpret_cast<const int4*>(w + (size_t)(nbase + brow) * DIM_K + bq * 16);
    const float2* szG = reinterpret_cast<const float2*>(saz) + (nbase + brow);
    const uint32_t b_stg_off = (uint32_t)brow * ROWB + bq * 32;

    // ---- ldmatrix lane bases ----
    const uint32_t a_lane_off = (uint32_t)(m0w + (lid & 15)) * ROWB + ((lid >> 4) << 4);
    const uint32_t b_lane_off = (uint32_t)(n0w + (lid & 7) + ((lid >> 4) & 1) * 8) * ROWB
                                + (((lid >> 3) & 1) << 4);

    float d[2][4][4];
    #pragma unroll
    for (int i = 0; i < 2; ++i)
        #pragma unroll
        for (int j = 0; j < 4; ++j)
            #pragma unroll
            for (int k = 0; k < 4; ++k) d[i][j][k] = 0.f;

    int4 br[4];
    float2 sz;

    #define ISSUE_A(ks, abuf) do {                                        \
        const uint32_t st = sb + (abuf) * TILE_BYTES + a_stg_off;         \
        const __half* sa = aG + (ks) * KSTEP;                             \
        cp_async16(st, sa);                                               \
        cp_async16(st + a_sstep, sa + a_gstep);                           \
        cp_commit();                                                      \
    } while (0)

    #define LOAD_B(ks) do {                                               \
        const int4* srcb = wG + (ks) * 16;                                \
        br[0] = __ldg(srcb + 0);  br[1] = __ldg(srcb + 1);                \
        br[2] = __ldg(srcb + 2);  br[3] = __ldg(srcb + 3);                \
        sz = __ldg(szG + ((ks) >> 1) * DIM_N);                            \
    } while (0)

    #define STS_B(bbuf) do {                                              \
        char* dst = smem + OFF_B + (bbuf) * TILE_BYTES + b_stg_off;       \
        const float s = sz.x, z = sz.y;                                   \
        _Pragma("unroll")                                                 \
        for (int j = 0; j < 2; ++j) {                                     \
            int4 p = br[2 * j], q = br[2 * j + 1];                        \
            uint4 v;                                                      \
            v.x = pack2((float)(p.x - 8) * s + z, (float)(p.y - 8) * s + z); \
            v.y = pack2((float)(p.z - 8) * s + z, (float)(p.w - 8) * s + z); \
            v.z = pack2((float)(q.x - 8) * s + z, (float)(q.y - 8) * s + z); \
            v.w = pack2((float)(q.z - 8) * s + z, (float)(q.w - 8) * s + z); \
            *reinterpret_cast<uint4*>(dst + j * 16) = v;                  \
        }                                                                 \
    } while (0)

    // ---- prologue: A stages 0..2 in flight; B(0) dequanted into buf 0 ----
    ISSUE_A(0, 0);
    ISSUE_A(1, 1);
    ISSUE_A(2, 2);
    LOAD_B(0);
    STS_B(0);

    int abuf = 0, bbuf = 0;
    for (int ks = 0; ks < ITERS; ++ks) {
        asm volatile("cp.async.wait_group %0;" :: "n"(STAGES - 1));
        __syncthreads();   // A(ks) + B(ks) visible to all

        if (ks + 1 < ITERS) LOAD_B(ks + 1);   // global prefetch, hidden by compute

        const uint32_t aBase = sb + abuf * TILE_BYTES + a_lane_off;
        const uint32_t bBase = sb + OFF_B + bbuf * TILE_BYTES + b_lane_off;
        #pragma unroll
        for (int kc = 0; kc < 4; ++kc) {
            uint32_t a[2][4], b[4][2];
            #pragma unroll
            for (int mt = 0; mt < 2; ++mt)
                ldsm4(a[mt], aBase + (uint32_t)mt * (16 * ROWB) + kc * 32);
            #pragma unroll
            for (int nt = 0; nt < 2; ++nt) {
                uint32_t t[4];
                ldsm4(t, bBase + (uint32_t)nt * (16 * ROWB) + kc * 32);
                b[2 * nt][0] = t[0]; b[2 * nt][1] = t[1];
                b[2 * nt + 1][0] = t[2]; b[2 * nt + 1][1] = t[3];
            }
            #pragma unroll
            for (int mt = 0; mt < 2; ++mt)
                #pragma unroll
                for (int n8 = 0; n8 < 4; ++n8)
                    mma16816(d[mt][n8], a[mt], b[n8]);
        }

        __syncthreads();   // everyone done reading A(ks-buf) and B(bbuf)

        if (ks + 1 < ITERS) STS_B(bbuf ^ 1);
        if (ks + STAGES < ITERS) ISSUE_A(ks + STAGES, abuf);
        else cp_commit();   // keep wait_group arithmetic valid in tail

        abuf = (abuf + 1 == STAGES) ? 0 : abuf + 1;
        bbuf ^= 1;
    }

    // ---- epilogue: registers -> gmem fp32 ----
    const int g = lid >> 2;
    const int tc = (lid & 3) * 2;
    #pragma unroll
    for (int mt = 0; mt < 2; ++mt) {
        const int row0 = mbase + m0w + mt * 16 + g;
        #pragma unroll
        for (int n8 = 0; n8 < 4; ++n8) {
            const int col = nbase + n0w + n8 * 8 + tc;
            float2 lo, hi;
            lo.x = d[mt][n8][0]; lo.y = d[mt][n8][1];
            hi.x = d[mt][n8][2]; hi.y = d[mt][n8][3];
            *reinterpret_cast<float2*>(out + (size_t)row0 * DIM_N + col) = lo;
            *reinterpret_cast<float2*>(out + (size_t)(row0 + 8) * DIM_N + col) = hi;
        }
    }
}

extern "C" void kernel_launch(void* const* d_in, const int* in_sizes, int n_in,
                              void* d_out, int out_size) {
    const float* x   = (const float*)d_in[0];
    const int*   w   = (const int*)d_in[1];
    const float* saz = (const float*)d_in[2];
    float* out = (float*)d_out;

    cudaFuncSetAttribute(gemm_kernel, cudaFuncAttributeMaxDynamicSharedMemorySize, SMEM_TOTAL);

    convert_x_kernel<<<(DIM_M * DIM_K / 8) / 256, 256>>>(x);
    gemm_kernel<<<GRID_MT * GRID_NT, 512, SMEM_TOTAL>>>(w, saz, out);
}

// round 7
// speedup vs baseline: 1.3202x; 1.3202x over previous
#include <cuda_runtime.h>
#include <cuda_fp16.h>
#include <cstdint>

// Problem dims (fixed per reference)
#define DIM_M 512
#define DIM_K 4096
#define DIM_N 11008

#define CTA_M 128
#define CTA_N 64
#define KSTEP 64                 // halves per K step
#define ITERS (DIM_K / KSTEP)    // 64
#define STAGES 4
#define GRID_MT (DIM_M / CTA_M)  // 4
#define GRID_NT (DIM_N / CTA_N)  // 172

// SMEM rows padded to 144B -> 8-row ldmatrix bases distinct mod 128 (conflict-free)
#define ROWB 144
#define A_TILE (128 * ROWB)                  // 18432
#define B_TILE (64 * ROWB)                   // 9216
#define STAGE_BYTES (A_TILE + B_TILE)        // 27648
#define SMEM_TOTAL (STAGES * STAGE_BYTES)    // 110592

// x converted to fp16, row-major [512][4096]
__device__ __align__(16) __half g_x16[DIM_M * DIM_K];
// weights dequantized to fp16, row-major [11008][4096]
__device__ __align__(16) __half g_w16[(size_t)DIM_N * DIM_K];

__device__ __forceinline__ uint32_t smem_u32(const void* p) {
    uint32_t a;
    asm("{ .reg .u64 t; cvta.to.shared.u64 t, %1; cvt.u32.u64 %0, t; }" : "=r"(a) : "l"(p));
    return a;
}

__device__ __forceinline__ void cp_async16(uint32_t dst, const void* src) {
    asm volatile("cp.async.cg.shared.global [%0], [%1], 16;" :: "r"(dst), "l"(src));
}
__device__ __forceinline__ void cp_commit() { asm volatile("cp.async.commit_group;"); }

__device__ __forceinline__ void ldsm4(uint32_t* r, uint32_t addr) {
    asm volatile("ldmatrix.sync.aligned.m8n8.x4.shared.b16 {%0,%1,%2,%3}, [%4];"
                 : "=r"(r[0]), "=r"(r[1]), "=r"(r[2]), "=r"(r[3]) : "r"(addr));
}

__device__ __forceinline__ void mma16816(float* d, const uint32_t* a, const uint32_t* b) {
    asm volatile(
        "mma.sync.aligned.m16n8k16.row.col.f32.f16.f16.f32 "
        "{%0,%1,%2,%3}, {%4,%5,%6,%7}, {%8,%9}, {%0,%1,%2,%3};"
        : "+f"(d[0]), "+f"(d[1]), "+f"(d[2]), "+f"(d[3])
        : "r"(a[0]), "r"(a[1]), "r"(a[2]), "r"(a[3]), "r"(b[0]), "r"(b[1]));
}

__device__ __forceinline__ uint32_t pack2(float a, float b) {
    __half2 h = __floats2half2_rn(a, b);
    return *reinterpret_cast<uint32_t*>(&h);
}

// ---------------- kernel 0: x fp32 -> fp16 row-major ----------------
__global__ void __launch_bounds__(256) convert_x_kernel(const float* __restrict__ x) {
    int gid = blockIdx.x * blockDim.x + threadIdx.x;
    const float4* src = reinterpret_cast<const float4*>(x) + gid * 2;
    float4 f0 = __ldg(src);
    float4 f1 = __ldg(src + 1);
    uint4 v;
    v.x = pack2(f0.x, f0.y);
    v.y = pack2(f0.z, f0.w);
    v.z = pack2(f1.x, f1.y);
    v.w = pack2(f1.z, f1.w);
    reinterpret_cast<uint4*>(g_x16)[gid] = v;
}

// ---------------- kernel 1: dequant weights int32(4bit codes) -> fp16 ----------------
__global__ void __launch_bounds__(256) dequant_w_kernel(const int* __restrict__ w,
                                                        const float* __restrict__ saz) {
    int gid = blockIdx.x * blockDim.x + threadIdx.x;   // N*K/8 threads
    int n = gid >> 9;                // DIM_K/8 = 512 chunks per row
    int kc = (gid & 511) << 3;
    int g = kc >> 7;                 // group of 128
    float2 sz = __ldg(reinterpret_cast<const float2*>(saz) + (size_t)g * DIM_N + n);
    const float s = sz.x, z = sz.y;
    const int4* src = reinterpret_cast<const int4*>(w + (size_t)n * DIM_K + kc);
    int4 a = __ldg(src);
    int4 b = __ldg(src + 1);
    uint4 v;
    v.x = pack2((float)(a.x - 8) * s + z, (float)(a.y - 8) * s + z);
    v.y = pack2((float)(a.z - 8) * s + z, (float)(a.w - 8) * s + z);
    v.z = pack2((float)(b.x - 8) * s + z, (float)(b.y - 8) * s + z);
    v.w = pack2((float)(b.z - 8) * s + z, (float)(b.w - 8) * s + z);
    reinterpret_cast<uint4*>(g_w16)[gid] = v;
}

// ---------------- kernel 2: fp16 HMMA GEMM, 4-stage single-sync pipeline ----------------
__global__ void __launch_bounds__(256, 2) gemm_kernel(float* __restrict__ out) {
    extern __shared__ __align__(1024) char smem[];
    const uint32_t sb = smem_u32(smem);
    const int tid = threadIdx.x;
    const int wid = tid >> 5;
    const int lid = tid & 31;

    // m-fast grid ordering: 4 CTAs sharing a weight N-tile run concurrently -> L2 reuse
    const int mtile = blockIdx.x & 3;
    const int ntile = blockIdx.x >> 2;
    const int mbase = mtile * CTA_M;
    const int nbase = ntile * CTA_N;

    // 4x2 warp grid, warp tile 32x32
    const int m0w = (wid & 3) * 32;
    const int n0w = (wid >> 2) * 32;

    // ---- loaders: A tile 128x8 chunks (4/thread), B tile 64x8 chunks (2/thread) ----
    const int r0 = tid >> 3;         // 0..31
    const int c  = tid & 7;          // 0..7
    const __half* aG = g_x16 + (size_t)(mbase + r0) * DIM_K + c * 8;
    const __half* bG = g_w16 + (size_t)(nbase + r0) * DIM_K + c * 8;
    const uint32_t ld_off = (uint32_t)r0 * ROWB + c * 16;
    const size_t gstep32 = (size_t)32 * DIM_K;
    const uint32_t sstep32 = 32u * ROWB;

    // ---- ldmatrix lane bases ----
    const uint32_t a_lane_off = (uint32_t)(m0w + (lid & 15)) * ROWB + ((lid >> 4) << 4);
    const uint32_t b_lane_off = (uint32_t)(n0w + (lid & 7) + ((lid >> 4) & 1) * 8) * ROWB
                                + (((lid >> 3) & 1) << 4);

    float d[2][4][4];
    #pragma unroll
    for (int i = 0; i < 2; ++i)
        #pragma unroll
        for (int j = 0; j < 4; ++j)
            #pragma unroll
            for (int k = 0; k < 4; ++k) d[i][j][k] = 0.f;

    #define ISSUE_STAGE(ks, buf) do {                                     \
        const uint32_t stA = sb + (buf) * STAGE_BYTES + ld_off;           \
        const __half* sa = aG + (ks) * KSTEP;                             \
        cp_async16(stA,               sa);                                \
        cp_async16(stA + sstep32,     sa + gstep32);                      \
        cp_async16(stA + 2 * sstep32, sa + 2 * gstep32);                  \
        cp_async16(stA + 3 * sstep32, sa + 3 * gstep32);                  \
        const uint32_t stB = stA + A_TILE;                                \
        const __half* sbp = bG + (ks) * KSTEP;                            \
        cp_async16(stB,           sbp);                                   \
        cp_async16(stB + sstep32, sbp + gstep32);                         \
    } while (0)

    // ---- prologue: stages 0..2 in flight ----
    #pragma unroll
    for (int s = 0; s < STAGES - 1; ++s) { ISSUE_STAGE(s, s); cp_commit(); }

    for (int ks = 0; ks < ITERS; ++ks) {
        asm volatile("cp.async.wait_group %0;" :: "n"(STAGES - 2));
        __syncthreads();

        // issue into the buffer consumed at iteration ks-1 (sync above certified it free)
        const int pf = ks + STAGES - 1;
        if (pf < ITERS) ISSUE_STAGE(pf, pf & (STAGES - 1));
        cp_commit();

        const int buf = ks & (STAGES - 1);
        const uint32_t aBase = sb + buf * STAGE_BYTES + a_lane_off;
        const uint32_t bBase = sb + buf * STAGE_BYTES + A_TILE + b_lane_off;
        #pragma unroll
        for (int kc = 0; kc < 4; ++kc) {
            uint32_t a[2][4], b[4][2];
            #pragma unroll
            for (int mt = 0; mt < 2; ++mt)
                ldsm4(a[mt], aBase + (uint32_t)mt * (16 * ROWB) + kc * 32);
            #pragma unroll
            for (int nt = 0; nt < 2; ++nt) {
                uint32_t t[4];
                ldsm4(t, bBase + (uint32_t)nt * (16 * ROWB) + kc * 32);
                b[2 * nt][0] = t[0]; b[2 * nt][1] = t[1];
                b[2 * nt + 1][0] = t[2]; b[2 * nt + 1][1] = t[3];
            }
            #pragma unroll
            for (int mt = 0; mt < 2; ++mt)
                #pragma unroll
                for (int n8 = 0; n8 < 4; ++n8)
                    mma16816(d[mt][n8], a[mt], b[n8]);
        }
    }

    // ---- epilogue: registers -> gmem fp32 ----
    const int g = lid >> 2;
    const int tc = (lid & 3) * 2;
    #pragma unroll
    for (int mt = 0; mt < 2; ++mt) {
        const int row0 = mbase + m0w + mt * 16 + g;
        #pragma unroll
        for (int n8 = 0; n8 < 4; ++n8) {
            const int col = nbase + n0w + n8 * 8 + tc;
            float2 lo, hi;
            lo.x = d[mt][n8][0]; lo.y = d[mt][n8][1];
            hi.x = d[mt][n8][2]; hi.y = d[mt][n8][3];
            *reinterpret_cast<float2*>(out + (size_t)row0 * DIM_N + col) = lo;
            *reinterpret_cast<float2*>(out + (size_t)(row0 + 8) * DIM_N + col) = hi;
        }
    }
}

extern "C" void kernel_launch(void* const* d_in, const int* in_sizes, int n_in,
                              void* d_out, int out_size) {
    const float* x   = (const float*)d_in[0];
    const int*   w   = (const int*)d_in[1];
    const float* saz = (const float*)d_in[2];
    float* out = (float*)d_out;

    cudaFuncSetAttribute(gemm_kernel, cudaFuncAttributeMaxDynamicSharedMemorySize, SMEM_TOTAL);

    convert_x_kernel<<<(DIM_M * DIM_K / 8) / 256, 256>>>(x);
    dequant_w_kernel<<<((size_t)DIM_N * DIM_K / 8) / 256, 256>>>(w, saz);
    gemm_kernel<<<GRID_MT * GRID_NT, 256, SMEM_TOTAL>>>(out);
}

// round 8
// speedup vs baseline: 1.3667x; 1.0352x over previous
#include <cuda_runtime.h>
#include <cuda_fp16.h>
#include <cstdint>

// Problem dims (fixed per reference)
#define DIM_M 512
#define DIM_K 4096
#define DIM_N 11008

#define CTA_M 128
#define CTA_N 128
#define KSTEP 64                 // halves per K step
#define ITERS (DIM_K / KSTEP)    // 64
#define STAGES 3
#define GRID_MT (DIM_M / CTA_M)  // 4
#define GRID_NT (DIM_N / CTA_N)  // 86

// SMEM rows padded to 144B -> 8-row ldmatrix bases distinct mod 128 (conflict-free)
#define ROWB 144
#define A_TILE (128 * ROWB)                  // 18432
#define B_TILE (128 * ROWB)                  // 18432
#define STAGE_BYTES (A_TILE + B_TILE)        // 36864
#define SMEM_TOTAL (STAGES * STAGE_BYTES)    // 110592  (x2 CTAs = 221184 <= 228KB)

// x converted to fp16, row-major [512][4096]
__device__ __align__(16) __half g_x16[DIM_M * DIM_K];
// weights dequantized to fp16, row-major [11008][4096]
__device__ __align__(16) __half g_w16[(size_t)DIM_N * DIM_K];

__device__ __forceinline__ uint32_t smem_u32(const void* p) {
    uint32_t a;
    asm("{ .reg .u64 t; cvta.to.shared.u64 t, %1; cvt.u32.u64 %0, t; }" : "=r"(a) : "l"(p));
    return a;
}

__device__ __forceinline__ void cp_async16(uint32_t dst, const void* src) {
    asm volatile("cp.async.cg.shared.global [%0], [%1], 16;" :: "r"(dst), "l"(src));
}
__device__ __forceinline__ void cp_commit() { asm volatile("cp.async.commit_group;"); }

__device__ __forceinline__ void ldsm4(uint32_t* r, uint32_t addr) {
    asm volatile("ldmatrix.sync.aligned.m8n8.x4.shared.b16 {%0,%1,%2,%3}, [%4];"
                 : "=r"(r[0]), "=r"(r[1]), "=r"(r[2]), "=r"(r[3]) : "r"(addr));
}

__device__ __forceinline__ void mma16816(float* d, const uint32_t* a, const uint32_t* b) {
    asm volatile(
        "mma.sync.aligned.m16n8k16.row.col.f32.f16.f16.f32 "
        "{%0,%1,%2,%3}, {%4,%5,%6,%7}, {%8,%9}, {%0,%1,%2,%3};"
        : "+f"(d[0]), "+f"(d[1]), "+f"(d[2]), "+f"(d[3])
        : "r"(a[0]), "r"(a[1]), "r"(a[2]), "r"(a[3]), "r"(b[0]), "r"(b[1]));
}

__device__ __forceinline__ uint32_t pack2(float a, float b) {
    __half2 h = __floats2half2_rn(a, b);
    return *reinterpret_cast<uint32_t*>(&h);
}

// ---------------- kernel 0: x fp32 -> fp16 row-major ----------------
__global__ void __launch_bounds__(256) convert_x_kernel(const float* __restrict__ x) {
    int gid = blockIdx.x * blockDim.x + threadIdx.x;
    const float4* src = reinterpret_cast<const float4*>(x) + gid * 2;
    float4 f0 = __ldg(src);
    float4 f1 = __ldg(src + 1);
    uint4 v;
    v.x = pack2(f0.x, f0.y);
    v.y = pack2(f0.z, f0.w);
    v.z = pack2(f1.x, f1.y);
    v.w = pack2(f1.z, f1.w);
    reinterpret_cast<uint4*>(g_x16)[gid] = v;
}

// ---------------- kernel 1: dequant weights int32(4bit codes) -> fp16 ----------------
__global__ void __launch_bounds__(256) dequant_w_kernel(const int* __restrict__ w,
                                                        const float* __restrict__ saz) {
    int gid = blockIdx.x * blockDim.x + threadIdx.x;   // N*K/8 threads
    int n = gid >> 9;                // DIM_K/8 = 512 chunks per row
    int kc = (gid & 511) << 3;
    int g = kc >> 7;                 // group of 128
    float2 sz = __ldg(reinterpret_cast<const float2*>(saz) + (size_t)g * DIM_N + n);
    const float s = sz.x, z = sz.y;
    const int4* src = reinterpret_cast<const int4*>(w + (size_t)n * DIM_K + kc);
    int4 a = __ldg(src);
    int4 b = __ldg(src + 1);
    uint4 v;
    v.x = pack2((float)(a.x - 8) * s + z, (float)(a.y - 8) * s + z);
    v.y = pack2((float)(a.z - 8) * s + z, (float)(a.w - 8) * s + z);
    v.z = pack2((float)(b.x - 8) * s + z, (float)(b.y - 8) * s + z);
    v.w = pack2((float)(b.z - 8) * s + z, (float)(b.w - 8) * s + z);
    reinterpret_cast<uint4*>(g_w16)[gid] = v;
}

// ---------------- kernel 2: fp16 HMMA GEMM, warp tile 64x32, single-sync pipeline ----------------
__global__ void __launch_bounds__(256, 2) gemm_kernel(float* __restrict__ out) {
    extern __shared__ __align__(1024) char smem[];
    const uint32_t sb = smem_u32(smem);
    const int tid = threadIdx.x;
    const int wid = tid >> 5;
    const int lid = tid & 31;

    // m-fast grid ordering: 4 CTAs sharing a weight N-tile run concurrently -> L2 reuse
    const int mtile = blockIdx.x & 3;
    const int ntile = blockIdx.x >> 2;
    const int mbase = mtile * CTA_M;
    const int nbase = ntile * CTA_N;

    // 2x4 warp grid, warp tile 64x32
    const int m0w = (wid & 1) * 64;
    const int n0w = (wid >> 1) * 32;

    // ---- loaders: each tile 128 rows x 8 chunks(16B) = 1024 chunks; 4 chunks/thread ----
    const int r0 = tid >> 3;         // 0..31
    const int c  = tid & 7;          // 0..7
    const __half* aG = g_x16 + (size_t)(mbase + r0) * DIM_K + c * 8;
    const __half* bG = g_w16 + (size_t)(nbase + r0) * DIM_K + c * 8;
    const uint32_t ld_off = (uint32_t)r0 * ROWB + c * 16;
    const size_t gstep32 = (size_t)32 * DIM_K;
    const uint32_t sstep32 = 32u * ROWB;

    // ---- ldmatrix lane bases ----
    const uint32_t a_lane_off = (uint32_t)(m0w + (lid & 15)) * ROWB + ((lid >> 4) << 4);
    const uint32_t b_lane_off = (uint32_t)(n0w + (lid & 7) + ((lid >> 4) & 1) * 8) * ROWB
                                + (((lid >> 3) & 1) << 4);

    float d[4][4][4];
    #pragma unroll
    for (int i = 0; i < 4; ++i)
        #pragma unroll
        for (int j = 0; j < 4; ++j)
            #pragma unroll
            for (int k = 0; k < 4; ++k) d[i][j][k] = 0.f;

    #define ISSUE_STAGE(ks, buf) do {                                     \
        const uint32_t stA = sb + (buf) * STAGE_BYTES + ld_off;           \
        const __half* sa = aG + (ks) * KSTEP;                             \
        cp_async16(stA,               sa);                                \
        cp_async16(stA + sstep32,     sa + gstep32);                      \
        cp_async16(stA + 2 * sstep32, sa + 2 * gstep32);                  \
        cp_async16(stA + 3 * sstep32, sa + 3 * gstep32);                  \
        const uint32_t stB = stA + A_TILE;                                \
        const __half* sbp = bG + (ks) * KSTEP;                            \
        cp_async16(stB,               sbp);                               \
        cp_async16(stB + sstep32,     sbp + gstep32);                     \
        cp_async16(stB + 2 * sstep32, sbp + 2 * gstep32);                 \
        cp_async16(stB + 3 * sstep32, sbp + 3 * gstep32);                 \
    } while (0)

    // ---- prologue: stages 0..1 in flight ----
    #pragma unroll
    for (int s = 0; s < STAGES - 1; ++s) { ISSUE_STAGE(s, s); cp_commit(); }

    int buf = 0;
    for (int ks = 0; ks < ITERS; ++ks) {
        asm volatile("cp.async.wait_group %0;" :: "n"(STAGES - 2));
        __syncthreads();

        // issue into the buffer consumed at iteration ks-1 (sync above certified it free)
        const int pf = ks + STAGES - 1;
        if (pf < ITERS) {
            const int pbuf = (buf + STAGES - 1) % STAGES;
            ISSUE_STAGE(pf, pbuf);
        }
        cp_commit();

        const uint32_t aBase = sb + buf * STAGE_BYTES + a_lane_off;
        const uint32_t bBase = sb + buf * STAGE_BYTES + A_TILE + b_lane_off;
        #pragma unroll
        for (int kc = 0; kc < 4; ++kc) {
            uint32_t a[4][4], b[4][2];
            #pragma unroll
            for (int mt = 0; mt < 4; ++mt)
                ldsm4(a[mt], aBase + (uint32_t)mt * (16 * ROWB) + kc * 32);
            #pragma unroll
            for (int nt = 0; nt < 2; ++nt) {
                uint32_t t[4];
                ldsm4(t, bBase + (uint32_t)nt * (16 * ROWB) + kc * 32);
                b[2 * nt][0] = t[0]; b[2 * nt][1] = t[1];
                b[2 * nt + 1][0] = t[2]; b[2 * nt + 1][1] = t[3];
            }
            #pragma unroll
            for (int mt = 0; mt < 4; ++mt)
                #pragma unroll
                for (int n8 = 0; n8 < 4; ++n8)
                    mma16816(d[mt][n8], a[mt], b[n8]);
        }

        if (++buf == STAGES) buf = 0;
    }

    // ---- epilogue: registers -> gmem fp32 ----
    const int g = lid >> 2;
    const int tc = (lid & 3) * 2;
    #pragma unroll
    for (int mt = 0; mt < 4; ++mt) {
        const int row0 = mbase + m0w + mt * 16 + g;
        #pragma unroll
        for (int n8 = 0; n8 < 4; ++n8) {
            const int col = nbase + n0w + n8 * 8 + tc;
            float2 lo, hi;
            lo.x = d[mt][n8][0]; lo.y = d[mt][n8][1];
            hi.x = d[mt][n8][2]; hi.y = d[mt][n8][3];
            *reinterpret_cast<float2*>(out + (size_t)row0 * DIM_N + col) = lo;
            *reinterpret_cast<float2*>(out + (size_t)(row0 + 8) * DIM_N + col) = hi;
        }
    }
}

extern "C" void kernel_launch(void* const* d_in, const int* in_sizes, int n_in,
                              void* d_out, int out_size) {
    const float* x   = (const float*)d_in[0];
    const int*   w   = (const int*)d_in[1];
    const float* saz = (const float*)d_in[2];
    float* out = (float*)d_out;

    cudaFuncSetAttribute(gemm_kernel, cudaFuncAttributeMaxDynamicSharedMemorySize, SMEM_TOTAL);

    convert_x_kernel<<<(DIM_M * DIM_K / 8) / 256, 256>>>(x);
    dequant_w_kernel<<<((size_t)DIM_N * DIM_K / 8) / 256, 256>>>(w, saz);
    gemm_kernel<<<GRID_MT * GRID_NT, 256, SMEM_TOTAL>>>(out);
}